// round 1
// baseline (speedup 1.0000x reference)
#include <cuda_runtime.h>
#include <math.h>

// ToneStack: 3 cascaded low-shelf biquads over x:[64, 480000] fp32.
// Exact blocked-recurrence decomposition:
//   pass_zero : per-chunk zero-state filtering -> final states f_k
//   scanA/B/C : hierarchical affine scan s_{k+1} = T s_k + f_k (T = A^CHUNK)
//   pass_final: per-chunk filtering from exact entry state, writes y.

#define TLEN   480000
#define NROW   64
#define CHUNK  256
#define NCHUNK 1875      // TLEN / CHUNK
#define NGSZ   25
#define NGROUP 75        // NCHUNK / NGSZ

__device__ float g_coef[15];                       // per stage: b0, c1, c2, -a1, -a2
__device__ float g_T[36];                          // A^CHUNK
__device__ float g_Tg[36];                         // A^(CHUNK*NGSZ)
__device__ float g_states[NROW * NCHUNK * 6];      // f_k then overwritten with entry states
__device__ float g_grp[NROW * NGROUP * 6];         // group zero-entry finals
__device__ float g_entry[NROW * NGROUP * 6];       // group entry states

// ---------------------------------------------------------------- setup ----

__device__ void shelf_coefs(double fc, double gdb, double Q, double* out) {
    const double PI = 3.14159265358979323846;
    double A  = pow(10.0, gdb / 40.0);
    double w0 = 2.0 * PI * fc / 48000.0;
    double al = sin(w0) / (2.0 * Q);
    double cw = cos(w0);
    double sq = sqrt(A);
    double b0 = A * ((A + 1.0) - (A - 1.0) * cw + 2.0 * sq * al);
    double b1 = 2.0 * A * ((A - 1.0) - (A + 1.0) * cw);
    double b2 = A * ((A + 1.0) - (A - 1.0) * cw - 2.0 * sq * al);
    double a0 = (A + 1.0) + (A - 1.0) * cw + 2.0 * sq * al;
    double a1 = -2.0 * ((A - 1.0) + (A + 1.0) * cw);
    double a2 = (A + 1.0) + (A - 1.0) * cw - 2.0 * sq * al;
    b0 /= a0; b1 /= a0; b2 /= a0; a1 /= a0; a2 /= a0;
    out[0] = b0;
    out[1] = b1 - a1 * b0;   // c1
    out[2] = b2 - a2 * b0;   // c2
    out[3] = -a1;
    out[4] = -a2;
}

// C = A*B (6x6), 36 threads; D must not alias A_/B_
#define MATMUL(D, A_, B_)                                                     \
    do {                                                                      \
        if (tid < 36) {                                                       \
            int r_ = tid / 6, c_ = tid % 6;                                   \
            float acc_ = 0.f;                                                 \
            for (int k_ = 0; k_ < 6; k_++)                                    \
                acc_ += (A_)[r_ * 6 + k_] * (B_)[k_ * 6 + c_];                \
            (D)[tid] = acc_;                                                  \
        }                                                                     \
        __syncthreads();                                                      \
    } while (0)

__global__ void setup_kernel(const float* lg, const float* mg, const float* mfc,
                             const float* mq, const float* hg) {
    __shared__ double scoef[15];
    __shared__ float M0[36], M1[36], M2[36], M3[36];
    int tid = threadIdx.x;

    if (tid == 0) {
        double c[5];
        shelf_coefs(120.0, (double)*lg, (double)0.707f, c);
        for (int i = 0; i < 5; i++) { scoef[i] = c[i];      g_coef[i]      = (float)c[i]; }
        shelf_coefs((double)*mfc, (double)*mg, (double)*mq, c);
        for (int i = 0; i < 5; i++) { scoef[5 + i] = c[i];  g_coef[5 + i]  = (float)c[i]; }
        shelf_coefs(4000.0, (double)*hg, (double)0.707f, c);
        for (int i = 0; i < 5; i++) { scoef[10 + i] = c[i]; g_coef[10 + i] = (float)c[i]; }
    }
    __syncthreads();

    // Build one-step 6x6 homogeneous matrix A: column j = step(e_j, x=0)
    if (tid < 6) {
        double z[6] = {0, 0, 0, 0, 0, 0};
        z[tid] = 1.0;
        double u = 0.0;
        double ns[6];
        for (int st = 0; st < 3; st++) {
            double b0  = scoef[st * 5 + 0], c1 = scoef[st * 5 + 1], c2 = scoef[st * 5 + 2];
            double na1 = scoef[st * 5 + 3], na2 = scoef[st * 5 + 4];
            double z1 = z[2 * st], z2 = z[2 * st + 1];
            double y = b0 * u + z1;
            ns[2 * st]     = c1 * u + na1 * z1 + z2;
            ns[2 * st + 1] = c2 * u + na2 * z1;
            u = y;
        }
        for (int i = 0; i < 6; i++) M0[i * 6 + tid] = (float)ns[i];
    }
    __syncthreads();

    // T = A^256 : 8 squarings, ping-pong M0 <-> M1
    for (int s = 0; s < 4; s++) {
        MATMUL(M1, M0, M0);
        MATMUL(M0, M1, M1);
    }
    if (tid < 36) g_T[tid] = M0[tid];
    __syncthreads();

    // Tg = T^25 = T^16 * T^8 * T
    MATMUL(M1, M0, M0);   // T^2
    MATMUL(M2, M1, M1);   // T^4
    MATMUL(M1, M2, M2);   // T^8
    MATMUL(M2, M1, M1);   // T^16
    MATMUL(M3, M2, M1);   // T^24
    MATMUL(M2, M3, M0);   // T^25
    if (tid < 36) g_Tg[tid] = M2[tid];
}

// -------------------------------------------------------------- filtering --

__device__ __forceinline__ float step_all(float u, float z[6], const float k[15]) {
    // stage 1
    float y0 = fmaf(k[0], u, z[0]);
    float t0 = fmaf(k[3], z[0], z[1]);
    z[1] = fmaf(k[2], u, k[4] * z[0]);
    z[0] = fmaf(k[1], u, t0);
    // stage 2
    float y1 = fmaf(k[5], y0, z[2]);
    float t1 = fmaf(k[8], z[2], z[3]);
    z[3] = fmaf(k[7], y0, k[9] * z[2]);
    z[2] = fmaf(k[6], y0, t1);
    // stage 3
    float y2 = fmaf(k[10], y1, z[4]);
    float t2 = fmaf(k[13], z[4], z[5]);
    z[5] = fmaf(k[12], y1, k[14] * z[4]);
    z[4] = fmaf(k[11], y1, t2);
    return y2;
}

__global__ __launch_bounds__(256) void pass_zero(const float* __restrict__ x) {
    int t = blockIdx.x * blockDim.x + threadIdx.x;
    if (t >= NROW * NCHUNK) return;
    int r = t / NCHUNK, c = t % NCHUNK;
    const float4* xp =
        reinterpret_cast<const float4*>(x + (size_t)r * TLEN + (size_t)c * CHUNK);
    float k[15];
#pragma unroll
    for (int i = 0; i < 15; i++) k[i] = g_coef[i];
    float z[6] = {0, 0, 0, 0, 0, 0};
#pragma unroll 4
    for (int i = 0; i < CHUNK / 4; i++) {
        float4 v = xp[i];
        step_all(v.x, z, k);
        step_all(v.y, z, k);
        step_all(v.z, z, k);
        step_all(v.w, z, k);
    }
    float* f = &g_states[(size_t)t * 6];
#pragma unroll
    for (int i = 0; i < 6; i++) f[i] = z[i];
}

__global__ __launch_bounds__(256) void pass_final(const float* __restrict__ x,
                                                  float* __restrict__ y) {
    int t = blockIdx.x * blockDim.x + threadIdx.x;
    if (t >= NROW * NCHUNK) return;
    int r = t / NCHUNK, c = t % NCHUNK;
    size_t off = (size_t)r * TLEN + (size_t)c * CHUNK;
    const float4* xp = reinterpret_cast<const float4*>(x + off);
    float4* yp = reinterpret_cast<float4*>(y + off);
    float k[15];
#pragma unroll
    for (int i = 0; i < 15; i++) k[i] = g_coef[i];
    float z[6];
    const float* si = &g_states[(size_t)t * 6];
#pragma unroll
    for (int i = 0; i < 6; i++) z[i] = si[i];
#pragma unroll 4
    for (int i = 0; i < CHUNK / 4; i++) {
        float4 v = xp[i];
        float4 o;
        o.x = step_all(v.x, z, k);
        o.y = step_all(v.y, z, k);
        o.z = step_all(v.z, z, k);
        o.w = step_all(v.w, z, k);
        yp[i] = o;
    }
}

// ------------------------------------------------------------------ scans --

__global__ void scanA() {
    int t = blockIdx.x * blockDim.x + threadIdx.x;
    if (t >= NROW * NGROUP) return;
    int r = t / NGROUP, g = t % NGROUP;
    float T[36];
#pragma unroll
    for (int i = 0; i < 36; i++) T[i] = g_T[i];
    float s[6] = {0, 0, 0, 0, 0, 0};
    const float* f = &g_states[((size_t)r * NCHUNK + (size_t)g * NGSZ) * 6];
    for (int i = 0; i < NGSZ; i++) {
        float fv[6], ns[6];
#pragma unroll
        for (int j = 0; j < 6; j++) fv[j] = f[i * 6 + j];
#pragma unroll
        for (int j = 0; j < 6; j++) {
            float acc = fv[j];
#pragma unroll
            for (int kk = 0; kk < 6; kk++) acc = fmaf(T[j * 6 + kk], s[kk], acc);
            ns[j] = acc;
        }
#pragma unroll
        for (int j = 0; j < 6; j++) s[j] = ns[j];
    }
    float* o = &g_grp[(size_t)t * 6];
#pragma unroll
    for (int j = 0; j < 6; j++) o[j] = s[j];
}

__global__ void scanB() {
    int r = threadIdx.x;
    if (r >= NROW) return;
    float T[36];
#pragma unroll
    for (int i = 0; i < 36; i++) T[i] = g_Tg[i];
    float s[6] = {0, 0, 0, 0, 0, 0};
    for (int g = 0; g < NGROUP; g++) {
        float* e = &g_entry[((size_t)r * NGROUP + g) * 6];
#pragma unroll
        for (int j = 0; j < 6; j++) e[j] = s[j];
        const float* fp = &g_grp[((size_t)r * NGROUP + g) * 6];
        float fv[6], ns[6];
#pragma unroll
        for (int j = 0; j < 6; j++) fv[j] = fp[j];
#pragma unroll
        for (int j = 0; j < 6; j++) {
            float acc = fv[j];
#pragma unroll
            for (int kk = 0; kk < 6; kk++) acc = fmaf(T[j * 6 + kk], s[kk], acc);
            ns[j] = acc;
        }
#pragma unroll
        for (int j = 0; j < 6; j++) s[j] = ns[j];
    }
}

__global__ void scanC() {
    int t = blockIdx.x * blockDim.x + threadIdx.x;
    if (t >= NROW * NGROUP) return;
    int r = t / NGROUP, g = t % NGROUP;
    float T[36];
#pragma unroll
    for (int i = 0; i < 36; i++) T[i] = g_T[i];
    float s[6];
    const float* e = &g_entry[(size_t)t * 6];
#pragma unroll
    for (int j = 0; j < 6; j++) s[j] = e[j];
    float* f = &g_states[((size_t)r * NCHUNK + (size_t)g * NGSZ) * 6];
    for (int i = 0; i < NGSZ; i++) {
        float fv[6], ns[6];
#pragma unroll
        for (int j = 0; j < 6; j++) fv[j] = f[i * 6 + j];
#pragma unroll
        for (int j = 0; j < 6; j++) f[i * 6 + j] = s[j];  // entry state for this chunk
#pragma unroll
        for (int j = 0; j < 6; j++) {
            float acc = fv[j];
#pragma unroll
            for (int kk = 0; kk < 6; kk++) acc = fmaf(T[j * 6 + kk], s[kk], acc);
            ns[j] = acc;
        }
#pragma unroll
        for (int j = 0; j < 6; j++) s[j] = ns[j];
    }
}

// ----------------------------------------------------------------- launch --

extern "C" void kernel_launch(void* const* d_in, const int* in_sizes, int n_in,
                              void* d_out, int out_size) {
    const float* x   = (const float*)d_in[0];
    const float* lg  = (const float*)d_in[1];
    const float* mg  = (const float*)d_in[2];
    const float* mfc = (const float*)d_in[3];
    const float* mq  = (const float*)d_in[4];
    const float* hg  = (const float*)d_in[5];
    float* y = (float*)d_out;

    setup_kernel<<<1, 64>>>(lg, mg, mfc, mq, hg);

    int nth = NROW * NCHUNK;
    int blocks = (nth + 255) / 256;
    pass_zero<<<blocks, 256>>>(x);

    int ng = NROW * NGROUP;
    scanA<<<(ng + 127) / 128, 128>>>();
    scanB<<<1, 64>>>();
    scanC<<<(ng + 127) / 128, 128>>>();

    pass_final<<<blocks, 256>>>(x, y);
}